// round 1
// baseline (speedup 1.0000x reference)
#include <cuda_runtime.h>
#include <math.h>

#define LTOK 31744          // 31*32*32
#define CIN  64
#define DI   128
#define DS   16
#define NXP  36             // DT_RANK + 2*DS
#define LC   64             // scan chunk length
#define NCH  (LTOK/LC)      // 496
#define NT   (LTOK/64)      // 496 token tiles of 64

// ---- scratch layout (floats) ----
#define L64  (LTOK*64)
#define L128 (LTOK*128)
#define L256 (LTOK*256)
#define L32  (LTOK*32)
#define PSZ  (NCH*DI*DS)

#define OFF_XT    0
#define OFF_XN    (OFF_XT + L64)
#define OFF_XIZ   (OFF_XN + L64)
#define OFF_XC    (OFF_XIZ + L256)
#define OFF_DELTA (OFF_XC + L128)
#define OFF_BC    (OFF_DELTA + L128)
#define OFF_P     (OFF_BC + L32)
#define OFF_S     (OFF_P + PSZ)
#define OFF_H0    (OFF_S + PSZ)
#define OFF_YZ    (OFF_H0 + PSZ)
#define OFF_XT2   (OFF_YZ + L128)
#define OFF_HN    (OFF_XT2 + L64)
#define OFF_GG    (OFF_HN + L64)
#define SCRATCH_TOTAL (OFF_GG + L128)

__device__ float g_scratch[SCRATCH_TOTAL];

// ============================================================
// K1: transpose [C, L] -> [L, C] and LayerNorm over C=64
// ============================================================
__global__ void k_ln1(const float* __restrict__ x, const float* __restrict__ w,
                      const float* __restrict__ b, float* __restrict__ xt,
                      float* __restrict__ xn)
{
    __shared__ float s[64 * 65];
    __shared__ float mu[64], rs[64];
    int l0 = blockIdx.x * 64;
    for (int idx = threadIdx.x; idx < 4096; idx += 256) {
        int c = idx >> 6, i = idx & 63;
        s[i * 65 + c] = x[c * LTOK + l0 + i];
    }
    __syncthreads();
    if (threadIdx.x < 64) {
        int i = threadIdx.x;
        float m = 0.f;
        #pragma unroll 8
        for (int c = 0; c < 64; c++) m += s[i * 65 + c];
        m *= (1.f / 64.f);
        float v = 0.f;
        #pragma unroll 8
        for (int c = 0; c < 64; c++) { float d = s[i * 65 + c] - m; v += d * d; }
        v *= (1.f / 64.f);
        mu[i] = m; rs[i] = rsqrtf(v + 1e-5f);
    }
    __syncthreads();
    for (int idx = threadIdx.x; idx < 4096; idx += 256) {
        int i = idx >> 6, c = idx & 63;
        float val = s[i * 65 + c];
        xt[(l0 + i) * 64 + c] = val;
        xn[(l0 + i) * 64 + c] = (val - mu[i]) * rs[i] * w[c] + b[c];
    }
}

// ============================================================
// Generic persistent register-tiled GEMM: Y[L,N] = X[L,K] @ W[K,N]
// EPI 0: plain store (N-stride)
// EPI 1: gated FFN1: Y[l,c] = silu(out[l,c]) * out[l,c+128], c<128
// EPI 2: out-proj: v = acc + R; Y=xt2=v; Y2=hn=LN(v)*lw+lb
// EPI 3: final:    v = acc + R; Y[c*L + l] = v (transposed output)
// Threads: 256. Tile: 64 tokens. Thread (tx,ty): rows ty*8+i, cols tx+32*j.
// ============================================================
template<int K, int N, int RC, int EPI>
__global__ void k_gemm(const float* __restrict__ X, const float* __restrict__ W,
                       float* __restrict__ Y, const float* __restrict__ R,
                       const float* __restrict__ lw, const float* __restrict__ lb,
                       float* __restrict__ Y2)
{
    extern __shared__ float sm[];
    float* sW = sm;             // K*N
    float* sX = sm + K * N;     // 64*K (reused as 64x65 tile in EPI 2/3)
    __shared__ float smu[64], srs[64];
    int tid = threadIdx.x, tx = tid & 31, ty = tid >> 5;

    for (int i = tid; i < K * N; i += 256) sW[i] = W[i];
    __syncthreads();

    for (int tile = blockIdx.x; tile < NT; tile += gridDim.x) {
        int l0 = tile * 64;
        for (int i = tid; i < 64 * K; i += 256) sX[i] = X[l0 * K + i];
        __syncthreads();

        float acc[8][RC];
        #pragma unroll
        for (int i = 0; i < 8; i++)
            #pragma unroll
            for (int j = 0; j < RC; j++) acc[i][j] = 0.f;

        #pragma unroll 2
        for (int k4 = 0; k4 < K; k4 += 4) {
            float4 xv[8];
            #pragma unroll
            for (int i = 0; i < 8; i++)
                xv[i] = *reinterpret_cast<const float4*>(&sX[(ty * 8 + i) * K + k4]);
            #pragma unroll
            for (int kk = 0; kk < 4; kk++) {
                float wv[RC];
                #pragma unroll
                for (int j = 0; j < RC; j++) wv[j] = sW[(k4 + kk) * N + tx + 32 * j];
                #pragma unroll
                for (int i = 0; i < 8; i++) {
                    float xs = (kk == 0) ? xv[i].x : (kk == 1) ? xv[i].y
                             : (kk == 2) ? xv[i].z : xv[i].w;
                    #pragma unroll
                    for (int j = 0; j < RC; j++) acc[i][j] = fmaf(xs, wv[j], acc[i][j]);
                }
            }
        }
        __syncthreads();

        if (EPI == 0) {
            #pragma unroll
            for (int i = 0; i < 8; i++)
                #pragma unroll
                for (int j = 0; j < RC; j++)
                    Y[(l0 + ty * 8 + i) * N + tx + 32 * j] = acc[i][j];
        } else if (EPI == 1) {
            #pragma unroll
            for (int i = 0; i < 8; i++)
                #pragma unroll
                for (int j = 0; j < 4; j++) {
                    float g = acc[i][j], v = acc[i][j + 4];
                    float sg = g / (1.f + __expf(-g));
                    Y[(l0 + ty * 8 + i) * 128 + tx + 32 * j] = sg * v;
                }
        } else {
            float* sT = sX;  // 64 x 65
            #pragma unroll
            for (int i = 0; i < 8; i++)
                #pragma unroll
                for (int j = 0; j < RC; j++) {
                    int row = ty * 8 + i, col = tx + 32 * j;
                    sT[row * 65 + col] = acc[i][j] + R[(l0 + row) * 64 + col];
                }
            __syncthreads();
            if (EPI == 2) {
                if (tid < 64) {
                    float m = 0.f;
                    #pragma unroll 8
                    for (int c = 0; c < 64; c++) m += sT[tid * 65 + c];
                    m *= (1.f / 64.f);
                    float v = 0.f;
                    #pragma unroll 8
                    for (int c = 0; c < 64; c++) { float d = sT[tid * 65 + c] - m; v += d * d; }
                    v *= (1.f / 64.f);
                    smu[tid] = m; srs[tid] = rsqrtf(v + 1e-5f);
                }
                __syncthreads();
                for (int idx = tid; idx < 4096; idx += 256) {
                    int r = idx >> 6, c = idx & 63;
                    float v = sT[r * 65 + c];
                    Y[(l0 + r) * 64 + c] = v;
                    Y2[(l0 + r) * 64 + c] = (v - smu[r]) * srs[r] * lw[c] + lb[c];
                }
            } else {  // EPI == 3: transposed final store
                for (int idx = tid; idx < 4096; idx += 256) {
                    int ll = idx & 63, c = idx >> 6;
                    Y[c * LTOK + l0 + ll] = sT[ll * 65 + c];
                }
            }
            __syncthreads();
        }
    }
}

// ============================================================
// K3: causal depthwise conv(4) + ReLU, then xc@W_xproj -> (dt,B,C),
//     then delta = softplus(dt@W_dt + bias)
// ============================================================
__global__ void k_conv(const float* __restrict__ xiz, const float* __restrict__ cw,
                       const float* __restrict__ Wxp, const float* __restrict__ Wdt,
                       const float* __restrict__ bias,
                       float* __restrict__ xc, float* __restrict__ delta,
                       float* __restrict__ bcout)
{
    extern __shared__ float sm[];
    float* sxc  = sm;               // 64*128
    float* sWx  = sxc + 8192;       // 128*36
    float* sdbl = sWx + 4608;       // 64*36
    float* sWdt = sdbl + 2304;      // 4*128
    int tid = threadIdx.x;
    int l0 = blockIdx.x * 64;

    for (int i = tid; i < 4608; i += 256) sWx[i] = Wxp[i];
    for (int i = tid; i < 512; i += 256) sWdt[i] = Wdt[i];

    for (int idx = tid; idx < 8192; idx += 256) {
        int t = idx >> 7, d = idx & 127;
        int l = l0 + t;
        float acc = 0.f;
        #pragma unroll
        for (int j = 0; j < 4; j++) {
            int ls = l - 3 + j;
            float v = (ls >= 0) ? xiz[ls * 256 + d] : 0.f;
            acc = fmaf(cw[d * 4 + j], v, acc);
        }
        acc = fmaxf(acc, 0.f);
        sxc[t * 128 + d] = acc;
        xc[l * 128 + d] = acc;
    }
    __syncthreads();

    for (int idx = tid; idx < 64 * NXP; idx += 256) {
        int t = idx / NXP, n = idx % NXP;
        float acc = 0.f;
        #pragma unroll 8
        for (int dd = 0; dd < 128; dd++) acc = fmaf(sxc[t * 128 + dd], sWx[dd * NXP + n], acc);
        sdbl[t * NXP + n] = acc;
        if (n >= 4) bcout[(l0 + t) * 32 + (n - 4)] = acc;
    }
    __syncthreads();

    for (int idx = tid; idx < 8192; idx += 256) {
        int t = idx >> 7, d = idx & 127;
        float acc = bias[d];
        #pragma unroll
        for (int r = 0; r < 4; r++) acc = fmaf(sdbl[t * NXP + r], sWdt[r * 128 + d], acc);
        float sp = (acc > 20.f) ? acc : log1pf(__expf(acc));
        delta[(l0 + t) * 128 + d] = sp;
    }
}

// ============================================================
// Scan helpers: dA_s = exp(delta*A[s]); fast path exploits A[s]=(s+1)*A[0]
// ============================================================
__device__ __forceinline__ void compute_dA(float dl, float A0, const float* A,
                                           bool fast, float (&dA)[DS])
{
    if (fast) {
        float r = __expf(dl * A0);
        float r2 = r * r, r4 = r2 * r2, r8 = r4 * r4;
        dA[0] = r;        dA[1] = r2;       dA[2] = r2 * r;   dA[3] = r4;
        dA[4] = r4 * r;   dA[5] = r4 * r2;  dA[6] = r4 * dA[2]; dA[7] = r8;
        dA[8] = r8 * r;   dA[9] = r8 * r2;  dA[10] = r8 * dA[2]; dA[11] = r8 * r4;
        dA[12] = r8 * dA[4]; dA[13] = r8 * dA[5]; dA[14] = r8 * dA[6]; dA[15] = r8 * r8;
    } else {
        #pragma unroll
        for (int s = 0; s < DS; s++) dA[s] = __expf(dl * A[s]);
    }
}

__device__ __forceinline__ bool load_A(const float* __restrict__ Alog, int d,
                                       float (&A)[DS], float& A0)
{
    #pragma unroll
    for (int s = 0; s < DS; s++) A[s] = -__expf(Alog[d * DS + s]);
    A0 = A[0];
    bool fast = (A0 < 0.f);
    #pragma unroll
    for (int s = 0; s < DS; s++) {
        float t = (float)(s + 1) * A0;
        fast = fast && (fabsf(A[s] - t) <= 1e-3f * fabsf(t));
    }
    return fast;
}

// K4: per-chunk local scan -> chunk product P, chunk sum S
__global__ void k_scan1(const float* __restrict__ delta, const float* __restrict__ u,
                        const float* __restrict__ bc, const float* __restrict__ Alog,
                        float* __restrict__ Pg, float* __restrict__ Sg)
{
    __shared__ float sB[LC * DS];
    int c = blockIdx.x, d = threadIdx.x;
    int l0 = c * LC;
    for (int idx = d; idx < LC * DS; idx += 128) {
        int t = idx >> 4, s = idx & 15;
        sB[idx] = bc[(l0 + t) * 32 + s];
    }
    __syncthreads();

    float A[DS], A0;
    bool fast = load_A(Alog, d, A, A0);

    float P[DS], S[DS];
    #pragma unroll
    for (int s = 0; s < DS; s++) { P[s] = 1.f; S[s] = 0.f; }

    for (int t = 0; t < LC; t++) {
        float dl = delta[(l0 + t) * DI + d];
        float uu = u[(l0 + t) * DI + d];
        float du = dl * uu;
        float dA[DS];
        compute_dA(dl, A0, A, fast, dA);
        #pragma unroll
        for (int s = 0; s < DS; s++) {
            S[s] = fmaf(dA[s], S[s], du * sB[t * DS + s]);
            P[s] *= dA[s];
        }
    }
    int base = (c * DI + d) * DS;
    #pragma unroll
    for (int s = 0; s < DS; s++) { Pg[base + s] = P[s]; Sg[base + s] = S[s]; }
}

// K5: sequential carry across chunks per (d,s)
__global__ void k_carry(const float* __restrict__ Pg, const float* __restrict__ Sg,
                        float* __restrict__ H0)
{
    int i = blockIdx.x * blockDim.x + threadIdx.x;
    if (i >= DI * DS) return;
    float H = 0.f;
    for (int c = 0; c < NCH; c++) {
        int o = c * DI * DS + i;
        H0[o] = H;
        H = fmaf(Pg[o], H, Sg[o]);
    }
}

// K6: rescan with carry, emit yz = (y + u*D) * silu(z)
__global__ void k_scan2(const float* __restrict__ delta, const float* __restrict__ u,
                        const float* __restrict__ bc, const float* __restrict__ Alog,
                        const float* __restrict__ H0, const float* __restrict__ Dp,
                        const float* __restrict__ xiz, float* __restrict__ yz)
{
    __shared__ float sB[LC * DS], sC[LC * DS];
    int c = blockIdx.x, d = threadIdx.x;
    int l0 = c * LC;
    for (int idx = d; idx < LC * DS; idx += 128) {
        int t = idx >> 4, s = idx & 15;
        sB[idx] = bc[(l0 + t) * 32 + s];
        sC[idx] = bc[(l0 + t) * 32 + 16 + s];
    }
    __syncthreads();

    float A[DS], A0;
    bool fast = load_A(Alog, d, A, A0);

    float h[DS];
    #pragma unroll
    for (int s = 0; s < DS; s++) h[s] = H0[(c * DI + d) * DS + s];
    float Dd = Dp[d];

    for (int t = 0; t < LC; t++) {
        float dl = delta[(l0 + t) * DI + d];
        float uu = u[(l0 + t) * DI + d];
        float du = dl * uu;
        float dA[DS];
        compute_dA(dl, A0, A, fast, dA);
        float y = 0.f;
        #pragma unroll
        for (int s = 0; s < DS; s++) {
            h[s] = fmaf(dA[s], h[s], du * sB[t * DS + s]);
            y = fmaf(h[s], sC[t * DS + s], y);
        }
        y = fmaf(uu, Dd, y);
        float z = xiz[(l0 + t) * 256 + 128 + d];
        float sig = 1.f / (1.f + __expf(-z));
        yz[(l0 + t) * DI + d] = y * (z * sig);
    }
}

// ============================================================
// launch
// ============================================================
#define SM_G1 ((64 * 256 + 64 * 64) * 4)    // 81920
#define SM_G2 ((128 * 64 + 64 * 128) * 4)   // 65536
#define SM_CONV ((8192 + 4608 + 2304 + 512) * 4)  // 62464

extern "C" void kernel_launch(void* const* d_in, const int* in_sizes, int n_in,
                              void* d_out, int out_size)
{
    const float* x    = (const float*)d_in[0];
    const float* ln1w = (const float*)d_in[1];
    const float* ln1b = (const float*)d_in[2];
    const float* Win  = (const float*)d_in[3];
    const float* cw   = (const float*)d_in[4];
    const float* Wxp  = (const float*)d_in[5];
    const float* Wdt  = (const float*)d_in[6];
    const float* dtb  = (const float*)d_in[7];
    const float* Alog = (const float*)d_in[8];
    const float* Dssm = (const float*)d_in[9];
    const float* Wout = (const float*)d_in[10];
    const float* ln2w = (const float*)d_in[11];
    const float* ln2b = (const float*)d_in[12];
    const float* Wf1  = (const float*)d_in[13];
    const float* Wf2  = (const float*)d_in[14];
    float* out = (float*)d_out;

    float* sc = nullptr;
    cudaGetSymbolAddress((void**)&sc, g_scratch);

    float* xt    = sc + OFF_XT;
    float* xn    = sc + OFF_XN;
    float* xiz   = sc + OFF_XIZ;
    float* xc    = sc + OFF_XC;
    float* delta = sc + OFF_DELTA;
    float* bcb   = sc + OFF_BC;
    float* Pg    = sc + OFF_P;
    float* Sg    = sc + OFF_S;
    float* H0    = sc + OFF_H0;
    float* yzb   = sc + OFF_YZ;
    float* xt2   = sc + OFF_XT2;
    float* hn    = sc + OFF_HN;
    float* gg    = sc + OFF_GG;

    cudaFuncSetAttribute(k_gemm<64, 256, 8, 0>, cudaFuncAttributeMaxDynamicSharedMemorySize, SM_G1);
    cudaFuncSetAttribute(k_gemm<64, 256, 8, 1>, cudaFuncAttributeMaxDynamicSharedMemorySize, SM_G1);
    cudaFuncSetAttribute(k_gemm<128, 64, 2, 2>, cudaFuncAttributeMaxDynamicSharedMemorySize, SM_G2);
    cudaFuncSetAttribute(k_gemm<128, 64, 2, 3>, cudaFuncAttributeMaxDynamicSharedMemorySize, SM_G2);
    cudaFuncSetAttribute(k_conv, cudaFuncAttributeMaxDynamicSharedMemorySize, SM_CONV);

    // 1. transpose + LN1
    k_ln1<<<NT, 256>>>(x, ln1w, ln1b, xt, xn);
    // 2. xn @ W_in -> xi | z
    k_gemm<64, 256, 8, 0><<<296, 256, SM_G1>>>(xn, Win, xiz, nullptr, nullptr, nullptr, nullptr);
    // 3. conv + relu + xproj + delta
    k_conv<<<NT, 256, SM_CONV>>>(xiz, cw, Wxp, Wdt, dtb, xc, delta, bcb);
    // 4-6. chunked selective scan
    k_scan1<<<NCH, 128>>>(delta, xc, bcb, Alog, Pg, Sg);
    k_carry<<<8, 256>>>(Pg, Sg, H0);
    k_scan2<<<NCH, 128>>>(delta, xc, bcb, Alog, H0, Dssm, xiz, yzb);
    // 7. yz @ W_out + residual -> xt2, LN2 -> hn
    k_gemm<128, 64, 2, 2><<<296, 256, SM_G2>>>(yzb, Wout, xt2, xt, ln2w, ln2b, hn);
    // 8. hn @ W_ffn1, gated silu -> gg
    k_gemm<64, 256, 8, 1><<<296, 256, SM_G1>>>(hn, Wf1, gg, nullptr, nullptr, nullptr, nullptr);
    // 9. gg @ W_ffn2 + residual, transposed store -> out
    k_gemm<128, 64, 2, 3><<<296, 256, SM_G2>>>(gg, Wf2, out, xt2, nullptr, nullptr, nullptr);
}